// round 11
// baseline (speedup 1.0000x reference)
#include <cuda_runtime.h>
#include <cuda_bf16.h>
#include <cstdint>
#include <math.h>

#define Bb 4
#define Cc 512
#define Tt 4096
#define Ee 1024
#define Hh 16
#define Dd 64
#define Ff 256
#define CO 1536
#define EPS 1e-6f

typedef __nv_bfloat16 bf;

// ---------------- scratch ----------------
__device__ __align__(1024) bf g_xh[Bb*Tt*Cc],  g_xl[Bb*Tt*Cc];
__device__ __align__(1024) bf g_Qh[Bb*Tt*Ee],  g_Ql[Bb*Tt*Ee];
__device__ __align__(1024) bf g_Kh[Bb*Tt*Ee],  g_Kl[Bb*Tt*Ee];
__device__ __align__(1024) bf g_Vth[Bb*Ee*Tt], g_Vtl[Bb*Ee*Tt];
__device__ __align__(1024) bf g_Wqh[Ee*Cc],    g_Wql[Ee*Cc];
__device__ __align__(1024) bf g_Wkh[Ee*Cc],    g_Wkl[Ee*Cc];
__device__ __align__(1024) bf g_Wvh[Ee*Cc],    g_Wvl[Ee*Cc];
__device__ __align__(1024) bf g_Woh[Ee*Ee],    g_Wol[Ee*Ee];
__device__ __align__(1024) bf g_ph[Ff*Dd],     g_pl[Ff*Dd];
__device__ __align__(1024) bf g_Qph[Bb*Hh*Tt*Ff], g_Qpl[Bb*Hh*Tt*Ff];
__device__ __align__(1024) bf g_Kpth[Bb*Hh*Ff*Tt], g_Kptl[Bb*Hh*Ff*Tt];
__device__ __align__(1024) bf g_ah[Bb*Tt*Ee],  g_al[Bb*Tt*Ee];
__device__ __align__(1024) bf g_KVth[Bb*Hh*64*Ff], g_KVtl[Bb*Hh*64*Ff];
__device__ float g_KVt[Bb*Hh*64*Ff];
__device__ float g_Ksum[Bb*Hh*Ff];
__device__ unsigned g_c0, g_c1;

// ================= PTX helpers =================
__device__ __forceinline__ uint32_t s2u(const void* p){
    uint32_t a;
    asm("{ .reg .u64 t; cvta.to.shared.u64 t, %1; cvt.u32.u64 %0, t; }" : "=r"(a) : "l"(p));
    return a;
}
__device__ __forceinline__ uint32_t swz(uint32_t off){ return off ^ ((off >> 3) & 0x70); }    // 128B rows
__device__ __forceinline__ uint32_t swz64(uint32_t off){ return off ^ ((off >> 3) & 0x30); }  // 64B rows

__device__ __forceinline__ void ldsm4(uint32_t& r0, uint32_t& r1, uint32_t& r2, uint32_t& r3, uint32_t addr){
    asm volatile("ldmatrix.sync.aligned.m8n8.x4.shared.b16 {%0,%1,%2,%3}, [%4];"
        : "=r"(r0), "=r"(r1), "=r"(r2), "=r"(r3) : "r"(addr));
}
__device__ __forceinline__ void mma_bf16(float* c, const uint32_t* a, const uint32_t* b){
    asm volatile("mma.sync.aligned.m16n8k16.row.col.f32.bf16.bf16.f32 "
        "{%0,%1,%2,%3}, {%4,%5,%6,%7}, {%8,%9}, {%0,%1,%2,%3};"
        : "+f"(c[0]), "+f"(c[1]), "+f"(c[2]), "+f"(c[3])
        : "r"(a[0]), "r"(a[1]), "r"(a[2]), "r"(a[3]), "r"(b[0]), "r"(b[1]));
}
__device__ __forceinline__ void cpa16(uint32_t s, const void* g){
    asm volatile("cp.async.cg.shared.global [%0], [%1], 16;" :: "r"(s), "l"(g));
}
__device__ __forceinline__ void cpa_commit(){ asm volatile("cp.async.commit_group;" ::: "memory"); }
__device__ __forceinline__ void cpa_wait0(){ asm volatile("cp.async.wait_group 0;" ::: "memory"); }
__device__ __forceinline__ void cpa_wait1(){ asm volatile("cp.async.wait_group 1;" ::: "memory"); }
__device__ __forceinline__ void cpa_wait2(){ asm volatile("cp.async.wait_group 2;" ::: "memory"); }

__device__ __forceinline__ void split2(float a, bf& h, bf& l){
    h = __float2bfloat16(a);
    l = __float2bfloat16(a - __bfloat162float(h));
}

// ================= small kernels =================
__global__ void k_prep_proj(const float* __restrict__ proj){
    int i = blockIdx.x * 256 + threadIdx.x;
    if (i == 0){ g_c0 = 0; g_c1 = 0; }
    if (i < Ff*Dd){ bf hi, lo; split2(proj[i], hi, lo); g_ph[i] = hi; g_pl[i] = lo; }
    if (i < Bb*Hh*64*Ff) g_KVt[i] = 0.f;
    if (i < Bb*Hh*Ff)    g_Ksum[i] = 0.f;
}
__global__ void k_prep_x(const float* __restrict__ x, float* __restrict__ out){
    __shared__ float tile[32][33];
    int b = blockIdx.z, t0 = blockIdx.x*32, c0 = blockIdx.y*32;
    int tx = threadIdx.x, ty = threadIdx.y;
    for (int i = ty; i < 32; i += 8){
        float v = x[((size_t)b*Cc + c0 + i)*Tt + t0 + tx];
        tile[i][tx] = v;
        out[((size_t)b*CO + c0 + i)*Tt + t0 + tx] = v;
    }
    __syncthreads();
    for (int i = ty; i < 32; i += 8){
        bf hi, lo; split2(tile[tx][i], hi, lo);
        size_t o = ((size_t)b*Tt + t0 + i)*Cc + c0 + tx;
        g_xh[o] = hi; g_xl[o] = lo;
    }
}
__global__ void k_prep_w(const float* __restrict__ Wq, const float* __restrict__ Wk,
                         const float* __restrict__ Wv, const float* __restrict__ Wo){
    const int Nd = Ee;
    int z = blockIdx.z;
    int Kd = (z == 3) ? Ee : Cc;
    int k0 = blockIdx.y*32;
    if (k0 >= Kd) return;
    const float* W = z == 0 ? Wq : z == 1 ? Wk : z == 2 ? Wv : Wo;
    bf* Dh = z == 0 ? g_Wqh : z == 1 ? g_Wkh : z == 2 ? g_Wvh : g_Woh;
    bf* Dl = z == 0 ? g_Wql : z == 1 ? g_Wkl : z == 2 ? g_Wvl : g_Wol;
    __shared__ float tile[32][33];
    int n0 = blockIdx.x*32;
    int tx = threadIdx.x, ty = threadIdx.y;
    for (int i = ty; i < 32; i += 8)
        tile[i][tx] = W[(size_t)(k0 + i)*Nd + n0 + tx];
    __syncthreads();
    for (int i = ty; i < 32; i += 8){
        bf hi, lo; split2(tile[tx][i], hi, lo);
        size_t o = (size_t)(n0 + i)*Kd + k0 + tx;
        Dh[o] = hi; Dl[o] = lo;
    }
}
__global__ void k_cvt_kv(){
    int i = blockIdx.x * 256 + threadIdx.x;
    if (i < Bb*Hh*64*Ff){ bf h, l; split2(g_KVt[i], h, l); g_KVth[i] = h; g_KVtl[i] = l; }
}

// ================= tile loaders =================
template<int NROWS>   // 128B rows, SW128
__device__ __forceinline__ void load_tileN(uint32_t sbase, const bf* g, int row0, int stride, int k0, int tid){
#pragma unroll
    for (int i = 0; i < NROWS/32; i++){
        int idx = tid + i*256;
        int r = idx >> 3, kc = idx & 7;
        cpa16(sbase + swz((uint32_t)(r*128 + kc*16)), g + (size_t)(row0 + r)*stride + k0 + kc*8);
    }
}
// 64B rows (k-tile 32), SW64, 128 rows
__device__ __forceinline__ void load_tile64(uint32_t sbase, const bf* g, int row0, int stride, int k0, int tid){
#pragma unroll
    for (int i = 0; i < 2; i++){
        int idx = tid + i*256;
        int r = idx >> 2, kc = idx & 3;
        cpa16(sbase + swz64((uint32_t)(r*64 + kc*16)), g + (size_t)(row0 + r)*stride + k0 + kc*8);
    }
}

#define STAGE_BYTES 65536

// ================= persistent GEMM, 128x128 tile, k-tile 32, 2 CTAs/SM =================
#define STG32 32768
#define PERS_DSM (3*STG32 + 16512)   // 112.5 KB -> 2 CTAs per SM

template<int MODE>
__global__ __launch_bounds__(256, 2) void k_mmaP(float* __restrict__ outp){
    constexpr int NKT   = (MODE == 0) ? 16 : 32;        // k-tiles of 32
    constexpr int KA    = (MODE == 0) ? Cc : Ee;
    constexpr int TOTAL = (MODE == 0) ? 3072 : 1024;

    extern __shared__ __align__(1024) char dsm[];
    float* fb = (float*)(dsm + 3*STG32);   // 32 x 129 fp32
    __shared__ int s_cur, s_next;
    uint32_t sb = s2u(dsm);
    int tid = threadIdx.x, lane = tid & 31, w = tid >> 5;
    unsigned* ctr = (MODE == 0) ? &g_c0 : &g_c1;

    if (tid == 0){ s_cur = (int)atomicAdd(ctr, 1u); s_next = (int)atomicAdd(ctr, 1u); }
    __syncthreads();
    int cur = s_cur, nxt = s_next;
    if (cur >= TOTAL) return;

    const bf* Ahp = (MODE == 0) ? g_xh : g_ah;
    const bf* Alp = (MODE == 0) ? g_xl : g_al;

    auto decode = [&](int id, int& rowA, int& rowB, const bf*& Bh2, const bf*& Bl2, int& z){
        if (MODE == 0){
            z = id >> 10; int r = id & 1023;
            rowB = (r >> 7) * 128; rowA = (r & 127) * 128;
            Bh2 = z == 0 ? g_Wqh : z == 1 ? g_Wkh : g_Wvh;
            Bl2 = z == 0 ? g_Wql : z == 1 ? g_Wkl : g_Wvl;
        } else {
            z = 0;
            rowB = (id >> 7) * 128; rowA = (id & 127) * 128;
            Bh2 = g_Woh; Bl2 = g_Wol;
        }
    };
    // stage: Ah 8K | Al 8K | Bh 8K | Bl 8K  (k-tile 32)
    auto commitStage = [&](int slot, int rA, int rB, const bf* bh, const bf* bl, int k0){
        uint32_t st_ = sb + (uint32_t)slot * STG32;
        load_tile64(st_,         Ahp, rA, KA, k0, tid);
        load_tile64(st_ + 8192,  Alp, rA, KA, k0, tid);
        load_tile64(st_ + 16384, bh,  rB, KA, k0, tid);
        load_tile64(st_ + 24576, bl,  rB, KA, k0, tid);
        cpa_commit();
    };

    int rowA, rowB, zc; const bf *Bh2, *Bl2;
    decode(cur, rowA, rowB, Bh2, Bl2, zc);
    commitStage(0, rowA, rowB, Bh2, Bl2, 0);
    commitStage(1, rowA, rowB, Bh2, Bl2, 32);
    int committed = 2, s = 0;

    int rr = lane & 7, sub = lane >> 3;
    int wm = (w & 1) * 64, wn = (w >> 1) * 32;
    int arow = wm + rr + (sub & 1) * 8;
    int acb0 = (sub >> 1) * 16;
    int brow = wn + rr + (sub >> 1) * 8;
    int bcb0 = (sub & 1) * 16;
    int r0row = lane >> 2, c0 = (lane & 3) * 2;

    while (true){
        float acc[4][4][4];
#pragma unroll
        for (int i = 0; i < 4; i++)
#pragma unroll
            for (int j = 0; j < 4; j++)
#pragma unroll
                for (int c = 0; c < 4; c++) acc[i][j][c] = 0.f;

        for (int kt = 0; kt < NKT; kt++){
            int kt2 = kt + 2;
            if (kt2 < NKT){
                commitStage((s + 2) % 3, rowA, rowB, Bh2, Bl2, kt2*32); committed++;
            } else if (nxt < TOTAL){
                int rA2, rB2, z2; const bf *bh2, *bl2;
                decode(nxt, rA2, rB2, bh2, bl2, z2);
                commitStage((s + 2) % 3, rA2, rB2, bh2, bl2, (kt2 - NKT)*32); committed++;
            }
            int allowed = committed - s - 1;
            if (allowed >= 2) cpa_wait2(); else if (allowed == 1) cpa_wait1(); else cpa_wait0();
            __syncthreads();

            uint32_t st = sb + (uint32_t)(s % 3) * STG32;
#pragma unroll
            for (int ks = 0; ks < 2; ks++){
                uint32_t ahf[4][4], alf[4][4], bhf[4][2], blf[4][2];
#pragma unroll
                for (int i = 0; i < 4; i++){
                    uint32_t sa = swz64((uint32_t)((arow + i*16)*64 + acb0 + ks*32));
                    ldsm4(ahf[i][0], ahf[i][1], ahf[i][2], ahf[i][3], st + sa);
                    ldsm4(alf[i][0], alf[i][1], alf[i][2], alf[i][3], st + 8192 + sa);
                }
#pragma unroll
                for (int j2 = 0; j2 < 2; j2++){
                    uint32_t sa = swz64((uint32_t)((brow + j2*16)*64 + bcb0 + ks*32));
                    uint32_t r0, r1, r2, r3;
                    ldsm4(r0, r1, r2, r3, st + 16384 + sa);
                    bhf[j2*2][0] = r0; bhf[j2*2][1] = r1; bhf[j2*2+1][0] = r2; bhf[j2*2+1][1] = r3;
                    ldsm4(r0, r1, r2, r3, st + 24576 + sa);
                    blf[j2*2][0] = r0; blf[j2*2][1] = r1; blf[j2*2+1][0] = r2; blf[j2*2+1][1] = r3;
                }
#pragma unroll
                for (int i = 0; i < 4; i++)
#pragma unroll
                    for (int j = 0; j < 4; j++){
                        mma_bf16(acc[i][j], ahf[i], bhf[j]);
                        mma_bf16(acc[i][j], ahf[i], blf[j]);
                        mma_bf16(acc[i][j], alf[i], bhf[j]);
                    }
            }
            __syncthreads();
            s++;
        }

        int m0 = rowA, n0 = rowB;
        if (MODE == 0 && zc < 2){
            bf* Dh = zc ? g_Kh : g_Qh;
            bf* Dl = zc ? g_Kl : g_Ql;
#pragma unroll
            for (int i = 0; i < 4; i++)
#pragma unroll
                for (int j = 0; j < 4; j++)
#pragma unroll
                    for (int half = 0; half < 2; half++){
                        int row = m0 + wm + i*16 + r0row + half*8;
                        int col = n0 + wn + j*8 + c0;
                        bf h0, l0, h1, l1;
                        split2(acc[i][j][half*2], h0, l0);
                        split2(acc[i][j][half*2 + 1], h1, l1);
                        *(__nv_bfloat162*)&Dh[(size_t)row*Ee + col] = __nv_bfloat162{h0, h1};
                        *(__nv_bfloat162*)&Dl[(size_t)row*Ee + col] = __nv_bfloat162{l0, l1};
                    }
        } else {
            int b = m0 / Tt, t0 = m0 % Tt;
#pragma unroll
            for (int p = 0; p < 4; p++){
                if ((w & 1) == (p >> 1)){
                    int ibase = (p & 1) * 2;
#pragma unroll
                    for (int ii = 0; ii < 2; ii++)
#pragma unroll
                        for (int j = 0; j < 4; j++)
#pragma unroll
                            for (int half = 0; half < 2; half++){
                                int row = (ibase + ii)*16 + r0row + half*8 - (p & 1)*32;
                                int col = wn + j*8 + c0;
                                fb[row*129 + col]     = acc[ibase + ii][j][half*2];
                                fb[row*129 + col + 1] = acc[ibase + ii][j][half*2 + 1];
                            }
                }
                __syncthreads();
                if (MODE == 0){
                    for (int idx = tid; idx < 4096; idx += 256){
                        int n = idx >> 5, t = idx & 31;
                        bf h, l; split2(fb[t*129 + n], h, l);
                        size_t o = (size_t)(b*Ee + n0 + n)*Tt + t0 + p*32 + t;
                        g_Vth[o] = h; g_Vtl[o] = l;
                    }
                } else {
                    for (int idx = tid; idx < 4096; idx += 256){
                        int n = idx >> 5, t = idx & 31;
                        outp[(size_t)b*CO*Tt + (size_t)(Cc + n0 + n)*Tt + t0 + p*32 + t] = fb[t*129 + n];
                    }
                }
                __syncthreads();
            }
        }

        if (nxt >= TOTAL) break;
        cur = nxt;
        decode(cur, rowA, rowB, Bh2, Bl2, zc);
        if (tid == 0) s_next = (int)atomicAdd(ctr, 1u);
        __syncthreads();
        nxt = s_next;
    }
}

// ================= 128-tile mma kernel for kv (MODE 3) / attn (MODE 4) =================
#define MMA_DSM 196608

template<int MODE>
__global__ __launch_bounds__(256, 1) void k_mma(float* __restrict__ outp){
    constexpr int JMAX   = 2;
    constexpr int NBROWS = 64;
    constexpr int NKT    = (MODE == 3) ? 8 : 4;

    extern __shared__ __align__(1024) char dsm[];
    __shared__ float sden[128];
    __shared__ float sKs[256];
    uint32_t sb = s2u(dsm);
    int tid = threadIdx.x, lane = tid & 31, w = tid >> 5;
    int bz = blockIdx.z;
    int m0 = blockIdx.x * 128;

    const bf *Ahp, *Alp, *Bhp, *Blp;
    int rowA0, rowB0, strideA, strideB, k0base = 0;

    if (MODE == 3){
        Ahp = g_Kpth; Alp = g_Kptl;
        rowA0 = bz*Ff + m0; strideA = Tt;
        Bhp = g_Vth; Blp = g_Vtl;
        rowB0 = (bz >> 4)*Ee + (bz & 15)*Dd; strideB = Tt;
        k0base = blockIdx.y * 512;
    } else {
        Ahp = g_Qph; Alp = g_Qpl;
        rowA0 = bz*Tt + m0; strideA = Ff;
        Bhp = g_KVth; Blp = g_KVtl;
        rowB0 = bz*64; strideB = Ff;
    }

    if (MODE == 4){
        if (tid < 128) sden[tid] = 0.f;
        sKs[tid] = g_Ksum[bz*Ff + tid];
    }

    float acc[4][JMAX][4];
#pragma unroll
    for (int i = 0; i < 4; i++)
#pragma unroll
        for (int j = 0; j < JMAX; j++)
#pragma unroll
            for (int c = 0; c < 4; c++) acc[i][j][c] = 0.f;

#define LOADSTG(s, k0) do { \
        uint32_t st_ = sb + (uint32_t)(s)*STAGE_BYTES; \
        load_tileN<128>(st_,         Ahp, rowA0, strideA, (k0), tid); \
        load_tileN<128>(st_ + 16384, Alp, rowA0, strideA, (k0), tid); \
        load_tileN<NBROWS>(st_ + 32768,                Bhp, rowB0, strideB, (k0), tid); \
        load_tileN<NBROWS>(st_ + 32768 + NBROWS*128,   Blp, rowB0, strideB, (k0), tid); \
        cpa_commit(); \
    } while(0)

    LOADSTG(0, k0base);
    if (NKT > 1) LOADSTG(1, k0base + 64);

    int rr = lane & 7, sub = lane >> 3;
    int wm = (w & 1) * 64, wn = (w >> 1) * (JMAX * 8);
    int arow = wm + rr + (sub & 1) * 8;
    int acb0 = (sub >> 1) * 16;
    int brow = wn + rr + (sub >> 1) * 8;
    int bcb0 = (sub & 1) * 16;
    const uint32_t blo = 32768u + NBROWS*128u;

    for (int kt = 0; kt < NKT; kt++){
        uint32_t st = sb + (uint32_t)(kt % 3) * STAGE_BYTES;
        if (kt + 2 < NKT) LOADSTG((kt + 2) % 3, k0base + (kt + 2)*64);
        int rem = NKT - 1 - kt;
        if (rem >= 2) cpa_wait2(); else if (rem == 1) cpa_wait1(); else cpa_wait0();
        __syncthreads();

#pragma unroll
        for (int ks = 0; ks < 4; ks++){
            uint32_t ahf[4][4], alf[4][4], bhf[JMAX][2], blf[JMAX][2];
#pragma unroll
            for (int i = 0; i < 4; i++){
                uint32_t sa = swz((uint32_t)((arow + i*16)*128 + acb0 + ks*32));
                ldsm4(ahf[i][0], ahf[i][1], ahf[i][2], ahf[i][3], st + sa);
                ldsm4(alf[i][0], alf[i][1], alf[i][2], alf[i][3], st + 16384 + sa);
            }
            {
                uint32_t sa = swz((uint32_t)(brow*128 + bcb0 + ks*32));
                uint32_t r0, r1, r2, r3;
                ldsm4(r0, r1, r2, r3, st + 32768 + sa);
                bhf[0][0] = r0; bhf[0][1] = r1; bhf[1][0] = r2; bhf[1][1] = r3;
                ldsm4(r0, r1, r2, r3, st + blo + sa);
                blf[0][0] = r0; blf[0][1] = r1; blf[1][0] = r2; blf[1][1] = r3;
            }
#pragma unroll
            for (int i = 0; i < 4; i++)
#pragma unroll
                for (int j = 0; j < JMAX; j++){
                    mma_bf16(acc[i][j], ahf[i], bhf[j]);
                    mma_bf16(acc[i][j], ahf[i], blf[j]);
                    mma_bf16(acc[i][j], alf[i], bhf[j]);
                }
        }
        if (MODE == 4){
            int row = tid & 127, fh = (tid >> 7) * 32;
            const char* sp = dsm + (size_t)(kt % 3) * STAGE_BYTES;
            float part = 0.f;
#pragma unroll
            for (int jj = 0; jj < 32; jj++){
                int fl = fh + ((jj + lane) & 31);
                uint32_t off = swz((uint32_t)(row*128 + fl*2));
                float hi = __bfloat162float(*(const bf*)(sp + off));
                float lo = __bfloat162float(*(const bf*)(sp + 16384 + off));
                part += (hi + lo) * sKs[kt*64 + fl];
            }
            atomicAdd(&sden[row], part);
        }
        __syncthreads();
    }
#undef LOADSTG

    int r0row = lane >> 2, c0 = (lane & 3) * 2;
    float* fb = (float*)dsm;

    if (MODE == 3){
#pragma unroll
        for (int i = 0; i < 4; i++)
#pragma unroll
            for (int j = 0; j < JMAX; j++)
#pragma unroll
                for (int half = 0; half < 2; half++){
                    int row = wm + i*16 + r0row + half*8;
                    int col = wn + j*8 + c0;
                    fb[row*129 + col]     = acc[i][j][half*2];
                    fb[row*129 + col + 1] = acc[i][j][half*2 + 1];
                }
        __syncthreads();
        for (int idx = tid; idx < 8192; idx += 256){
            int n = idx >> 7, f = idx & 127;
            atomicAdd(&g_KVt[((size_t)bz*64 + n)*Ff + m0 + f], fb[f*129 + n]);
        }
    } else {
        int b = bz >> 4, h = bz & 15;
#pragma unroll
        for (int i = 0; i < 4; i++)
#pragma unroll
            for (int half = 0; half < 2; half++){
                int row = wm + i*16 + r0row + half*8;
                float inv = 1.0f / fmaxf(sden[row], 1e-6f);
#pragma unroll
                for (int j = 0; j < JMAX; j++){
                    int col = wn + j*8 + c0;
                    bf h0, l0, h1, l1;
                    split2(acc[i][j][half*2] * inv, h0, l0);
                    split2(acc[i][j][half*2 + 1] * inv, h1, l1);
                    size_t o = (size_t)(b*Tt + m0 + row)*Ee + h*Dd + col;
                    *(__nv_bfloat162*)&g_ah[o] = __nv_bfloat162{h0, h1};
                    *(__nv_bfloat162*)&g_al[o] = __nv_bfloat162{l0, l1};
                }
            }
    }
}

// ================= feature-map kernel: proj resident, Q AND K in one block (8 m-iters) =================
#define FEAT_DSM (32768 + 65536 + 66048)

__global__ __launch_bounds__(256, 1) void k_featm(){
    extern __shared__ __align__(1024) char dsm[];
    uint32_t sb = s2u(dsm);
    int tid = threadIdx.x, lane = tid & 31, w = tid >> 5;
    int bh = blockIdx.z;
    int m0 = blockIdx.x * 512, n0 = blockIdx.y * 128;
    int hoff = (bh & 15)*Dd;
    int rowBase = (bh >> 4)*Tt + m0;

    auto srcH = [&](int it){ return (it < 4 ? g_Qh : g_Kh) + hoff; };
    auto srcL = [&](int it){ return (it < 4 ? g_Ql : g_Kl) + hoff; };

    load_tileN<128>(sb,         g_ph, n0, Dd, 0, tid);
    load_tileN<128>(sb + 16384, g_pl, n0, Dd, 0, tid);
    load_tileN<128>(sb + 32768,         srcH(0), rowBase, Ee, 0, tid);
    load_tileN<128>(sb + 32768 + 16384, srcL(0), rowBase, Ee, 0, tid);
    cpa_commit();
    load_tileN<128>(sb + 65536,         srcH(1), rowBase + 128, Ee, 0, tid);
    load_tileN<128>(sb + 65536 + 16384, srcL(1), rowBase + 128, Ee, 0, tid);
    cpa_commit();

    int rr = lane & 7, sub = lane >> 3;
    int wm = (w & 1) * 64, wn = (w >> 1) * 32;
    int arow = wm + rr + (sub & 1) * 8;
    int acb0 = (sub >> 1) * 16;
    int brow = wn + rr + (sub >> 1) * 8;
    int bcb0 = (sub & 1) * 16;
    float* fb = (float*)(dsm + 32768 + 65536);

    for (int it = 0; it < 8; it++){
        uint32_t stA = sb + 32768 + (uint32_t)(it & 1) * 32768;
        if (it < 7) cpa_wait1(); else cpa_wait0();
        __syncthreads();

        float acc[4][4][4];
#pragma unroll
        for (int i = 0; i < 4; i++)
#pragma unroll
            for (int j = 0; j < 4; j++)
#pragma unroll
                for (int c = 0; c < 4; c++) acc[i][j][c] = 0.f;

#pragma unroll
        for (int ks = 0; ks < 4; ks++){
            uint32_t ahf[4][4], alf[4][4], bhf[4][2], blf[4][2];
#pragma unroll
            for (int i = 0; i < 4; i++){
                uint32_t sa = swz((uint32_t)((arow + i*16)*128 + acb0 + ks*32));
                ldsm4(ahf[i][0], ahf[i][1], ahf[i][2], ahf[i][3], stA + sa);
                ldsm4(alf[i][0], alf[i][1], alf[i][2], alf[i][3], stA + 16384 + sa);
            }
#pragma unroll
            for (int j2 = 0; j2 < 2; j2++){
                uint32_t sa = swz((uint32_t)((brow + j2*16)*128 + bcb0 + ks*32));
                uint32_t r0, r1, r2, r3;
                ldsm4(r0, r1, r2, r3, sb + sa);
                bhf[j2*2][0] = r0; bhf[j2*2][1] = r1; bhf[j2*2+1][0] = r2; bhf[j2*2+1][1] = r3;
                ldsm4(r0, r1, r2, r3, sb + 16384 + sa);
                blf[j2*2][0] = r0; blf[j2*2][1] = r1; blf[j2*2+1][0] = r2; blf[j2*2+1][1] = r3;
            }
#pragma unroll
            for (int i = 0; i < 4; i++)
#pragma unroll
                for (int j = 0; j < 4; j++){
                    mma_bf16(acc[i][j], ahf[i], bhf[j]);
                    mma_bf16(acc[i][j], ahf[i], blf[j]);
                    mma_bf16(acc[i][j], alf[i], bhf[j]);
                }
        }
        __syncthreads();
        if (it + 2 < 8){
            load_tileN<128>(stA,         srcH(it + 2), rowBase + ((it + 2) & 3)*128, Ee, 0, tid);
            load_tileN<128>(stA + 16384, srcL(it + 2), rowBase + ((it + 2) & 3)*128, Ee, 0, tid);
            cpa_commit();
        }

        int r0row = lane >> 2, c0 = (lane & 3) * 2;
        int mt = (it & 3) * 128;
        if (it < 4){
#pragma unroll
            for (int i = 0; i < 4; i++)
#pragma unroll
                for (int j = 0; j < 4; j++)
#pragma unroll
                    for (int half = 0; half < 2; half++){
                        int row = wm + i*16 + r0row + half*8;
                        int col = wn + j*8 + c0;
                        bf h0, l0, h1, l1;
                        split2(expf(acc[i][j][half*2]) + EPS, h0, l0);
                        split2(expf(acc[i][j][half*2 + 1]) + EPS, h1, l1);
                        size_t o = (size_t)(bh*Tt + m0 + mt + row)*Ff + n0 + col;
                        *(__nv_bfloat162*)&g_Qph[o] = __nv_bfloat162{h0, h1};
                        *(__nv_bfloat162*)&g_Qpl[o] = __nv_bfloat162{l0, l1};
                    }
        } else {
#pragma unroll
            for (int i = 0; i < 4; i++)
#pragma unroll
                for (int j = 0; j < 4; j++)
#pragma unroll
                    for (int half = 0; half < 2; half++){
                        int row = wm + i*16 + r0row + half*8;
                        int col = wn + j*8 + c0;
                        fb[row*129 + col]     = expf(acc[i][j][half*2]) + EPS;
                        fb[row*129 + col + 1] = expf(acc[i][j][half*2 + 1]) + EPS;
                    }
            __syncthreads();
            for (int idx = tid; idx < 16384; idx += 256){
                int f = idx >> 7, t = idx & 127;
                bf h, l; split2(fb[t*129 + f], h, l);
                size_t o = (size_t)(bh*Ff + n0 + f)*Tt + m0 + mt + t;
                g_Kpth[o] = h; g_Kptl[o] = l;
            }
            {
                int f = tid >> 1, th = tid & 1;
                float s = 0.f;
#pragma unroll 8
                for (int t = th*64; t < th*64 + 64; t++) s += fb[t*129 + f];
                atomicAdd(&g_Ksum[bh*Ff + n0 + f], s);
            }
            __syncthreads();
        }
    }
}

// ================= launch =================
extern "C" void kernel_launch(void* const* d_in, const int* in_sizes, int n_in,
                              void* d_out, int out_size) {
    const float* x    = (const float*)d_in[0];
    const float* Wq   = (const float*)d_in[1];
    const float* Wk   = (const float*)d_in[2];
    const float* Wv   = (const float*)d_in[3];
    const float* Wo   = (const float*)d_in[4];
    const float* proj = (const float*)d_in[5];
    float* out = (float*)d_out;

    cudaFuncSetAttribute(k_mmaP<0>, cudaFuncAttributeMaxDynamicSharedMemorySize, PERS_DSM);
    cudaFuncSetAttribute(k_mmaP<1>, cudaFuncAttributeMaxDynamicSharedMemorySize, PERS_DSM);
    cudaFuncSetAttribute(k_mma<3>,  cudaFuncAttributeMaxDynamicSharedMemorySize, MMA_DSM);
    cudaFuncSetAttribute(k_mma<4>,  cudaFuncAttributeMaxDynamicSharedMemorySize, MMA_DSM);
    cudaFuncSetAttribute(k_featm,   cudaFuncAttributeMaxDynamicSharedMemorySize, FEAT_DSM);

    k_prep_proj<<<(Bb*Hh*64*Ff + 255)/256, 256>>>(proj);
    k_prep_x<<<dim3(Tt/32, Cc/32, Bb), dim3(32, 8)>>>(x, out);
    k_prep_w<<<dim3(Ee/32, Ee/32, 4), dim3(32, 8)>>>(Wq, Wk, Wv, Wo);

    k_mmaP<0><<<296, 256, PERS_DSM>>>(nullptr);                            // QKV (2 CTAs/SM)
    k_featm<<<dim3(Tt/512, Ff/128, Bb*Hh), 256, FEAT_DSM>>>();             // Qp + Kp + Ksum
    k_mma<3><<<dim3(Ff/128, 8, Bb*Hh), 256, MMA_DSM>>>(nullptr);           // KV
    k_cvt_kv<<<(Bb*Hh*64*Ff + 255)/256, 256>>>();
    k_mma<4><<<dim3(Tt/128, 1, Bb*Hh), 256, MMA_DSM>>>(nullptr);           // attn
    k_mmaP<1><<<296, 256, PERS_DSM>>>(out);                                // Wo + concat (2 CTAs/SM)
}

// round 12
// speedup vs baseline: 1.1126x; 1.1126x over previous
#include <cuda_runtime.h>
#include <cuda_bf16.h>
#include <cstdint>
#include <math.h>

#define Bb 4
#define Cc 512
#define Tt 4096
#define Ee 1024
#define Hh 16
#define Dd 64
#define Ff 256
#define CO 1536
#define EPS 1e-6f

typedef __nv_bfloat16 bf;

// ---------------- scratch ----------------
__device__ __align__(1024) bf g_xh[Bb*Tt*Cc],  g_xl[Bb*Tt*Cc];
__device__ __align__(1024) bf g_Qh[Bb*Tt*Ee],  g_Ql[Bb*Tt*Ee];
__device__ __align__(1024) bf g_Kh[Bb*Tt*Ee],  g_Kl[Bb*Tt*Ee];
__device__ __align__(1024) bf g_Vth[Bb*Ee*Tt], g_Vtl[Bb*Ee*Tt];
__device__ __align__(1024) bf g_Wqh[Ee*Cc],    g_Wql[Ee*Cc];
__device__ __align__(1024) bf g_Wkh[Ee*Cc],    g_Wkl[Ee*Cc];
__device__ __align__(1024) bf g_Wvh[Ee*Cc],    g_Wvl[Ee*Cc];
__device__ __align__(1024) bf g_Woh[Ee*Ee],    g_Wol[Ee*Ee];
__device__ __align__(1024) bf g_ph[Ff*Dd],     g_pl[Ff*Dd];
__device__ __align__(1024) bf g_Qph[Bb*Hh*Tt*Ff], g_Qpl[Bb*Hh*Tt*Ff];
__device__ __align__(1024) bf g_Kpth[Bb*Hh*Ff*Tt], g_Kptl[Bb*Hh*Ff*Tt];
__device__ __align__(1024) bf g_ah[Bb*Tt*Ee],  g_al[Bb*Tt*Ee];
__device__ __align__(1024) bf g_KVth[Bb*Hh*64*Ff], g_KVtl[Bb*Hh*64*Ff];
__device__ float g_KVt[Bb*Hh*64*Ff];
__device__ float g_Ksum[Bb*Hh*Ff];
__device__ unsigned g_c0, g_c1;

// ================= PTX helpers =================
__device__ __forceinline__ uint32_t s2u(const void* p){
    uint32_t a;
    asm("{ .reg .u64 t; cvta.to.shared.u64 t, %1; cvt.u32.u64 %0, t; }" : "=r"(a) : "l"(p));
    return a;
}
__device__ __forceinline__ uint32_t swz(uint32_t off){ return off ^ ((off >> 3) & 0x70); }

__device__ __forceinline__ void ldsm4(uint32_t& r0, uint32_t& r1, uint32_t& r2, uint32_t& r3, uint32_t addr){
    asm volatile("ldmatrix.sync.aligned.m8n8.x4.shared.b16 {%0,%1,%2,%3}, [%4];"
        : "=r"(r0), "=r"(r1), "=r"(r2), "=r"(r3) : "r"(addr));
}
__device__ __forceinline__ void mma_bf16(float* c, const uint32_t* a, const uint32_t* b){
    asm volatile("mma.sync.aligned.m16n8k16.row.col.f32.bf16.bf16.f32 "
        "{%0,%1,%2,%3}, {%4,%5,%6,%7}, {%8,%9}, {%0,%1,%2,%3};"
        : "+f"(c[0]), "+f"(c[1]), "+f"(c[2]), "+f"(c[3])
        : "r"(a[0]), "r"(a[1]), "r"(a[2]), "r"(a[3]), "r"(b[0]), "r"(b[1]));
}
__device__ __forceinline__ void cpa16(uint32_t s, const void* g){
    asm volatile("cp.async.cg.shared.global [%0], [%1], 16;" :: "r"(s), "l"(g));
}
__device__ __forceinline__ void cpa_commit(){ asm volatile("cp.async.commit_group;" ::: "memory"); }
__device__ __forceinline__ void cpa_wait0(){ asm volatile("cp.async.wait_group 0;" ::: "memory"); }
__device__ __forceinline__ void cpa_wait1(){ asm volatile("cp.async.wait_group 1;" ::: "memory"); }
__device__ __forceinline__ void cpa_wait2(){ asm volatile("cp.async.wait_group 2;" ::: "memory"); }

__device__ __forceinline__ void split2(float a, bf& h, bf& l){
    h = __float2bfloat16(a);
    l = __float2bfloat16(a - __bfloat162float(h));
}

// ================= small kernels =================
__global__ void k_prep_proj(const float* __restrict__ proj){
    int i = blockIdx.x * 256 + threadIdx.x;
    if (i == 0){ g_c0 = 0; g_c1 = 0; }
    if (i < Ff*Dd){ bf hi, lo; split2(proj[i], hi, lo); g_ph[i] = hi; g_pl[i] = lo; }
    if (i < Bb*Hh*64*Ff) g_KVt[i] = 0.f;
    if (i < Bb*Hh*Ff)    g_Ksum[i] = 0.f;
}
__global__ void k_prep_x(const float* __restrict__ x, float* __restrict__ out){
    __shared__ float tile[32][33];
    int b = blockIdx.z, t0 = blockIdx.x*32, c0 = blockIdx.y*32;
    int tx = threadIdx.x, ty = threadIdx.y;
    for (int i = ty; i < 32; i += 8){
        float v = x[((size_t)b*Cc + c0 + i)*Tt + t0 + tx];
        tile[i][tx] = v;
        out[((size_t)b*CO + c0 + i)*Tt + t0 + tx] = v;
    }
    __syncthreads();
    for (int i = ty; i < 32; i += 8){
        bf hi, lo; split2(tile[tx][i], hi, lo);
        size_t o = ((size_t)b*Tt + t0 + i)*Cc + c0 + tx;
        g_xh[o] = hi; g_xl[o] = lo;
    }
}
__global__ void k_prep_w(const float* __restrict__ Wq, const float* __restrict__ Wk,
                         const float* __restrict__ Wv, const float* __restrict__ Wo){
    const int Nd = Ee;
    int z = blockIdx.z;
    int Kd = (z == 3) ? Ee : Cc;
    int k0 = blockIdx.y*32;
    if (k0 >= Kd) return;
    const float* W = z == 0 ? Wq : z == 1 ? Wk : z == 2 ? Wv : Wo;
    bf* Dh = z == 0 ? g_Wqh : z == 1 ? g_Wkh : z == 2 ? g_Wvh : g_Woh;
    bf* Dl = z == 0 ? g_Wql : z == 1 ? g_Wkl : z == 2 ? g_Wvl : g_Wol;
    __shared__ float tile[32][33];
    int n0 = blockIdx.x*32;
    int tx = threadIdx.x, ty = threadIdx.y;
    for (int i = ty; i < 32; i += 8)
        tile[i][tx] = W[(size_t)(k0 + i)*Nd + n0 + tx];
    __syncthreads();
    for (int i = ty; i < 32; i += 8){
        bf hi, lo; split2(tile[tx][i], hi, lo);
        size_t o = (size_t)(n0 + i)*Kd + k0 + tx;
        Dh[o] = hi; Dl[o] = lo;
    }
}
__global__ void k_cvt_kv(){
    int i = blockIdx.x * 256 + threadIdx.x;
    if (i < Bb*Hh*64*Ff){ bf h, l; split2(g_KVt[i], h, l); g_KVth[i] = h; g_KVtl[i] = l; }
}

// ================= tile loaders =================
template<int NROWS>
__device__ __forceinline__ void load_tileN(uint32_t sbase, const bf* g, int row0, int stride, int k0, int tid){
#pragma unroll
    for (int i = 0; i < NROWS/32; i++){
        int idx = tid + i*256;
        int r = idx >> 3, kc = idx & 7;
        cpa16(sbase + swz((uint32_t)(r*128 + kc*16)), g + (size_t)(row0 + r)*stride + k0 + kc*8);
    }
}

#define STAGE_BYTES 65536

// ================= persistent GEMM: 128x128 tile, 64x32 warp tiles, 1 barrier/k-tile =================
#define PERS_DSM (3*STAGE_BYTES + 16512)

template<int MODE>
__global__ __launch_bounds__(256, 1) void k_mmaP(float* __restrict__ outp){
    constexpr int NKT   = (MODE == 0) ? 8 : 16;
    constexpr int KA    = (MODE == 0) ? Cc : Ee;
    constexpr int TOTAL = (MODE == 0) ? 3072 : 1024;

    extern __shared__ __align__(1024) char dsm[];
    float* fb = (float*)(dsm + 3*STAGE_BYTES);   // 32 x 129 fp32
    __shared__ int s_cur, s_next;
    uint32_t sb = s2u(dsm);
    int tid = threadIdx.x, lane = tid & 31, w = tid >> 5;
    unsigned* ctr = (MODE == 0) ? &g_c0 : &g_c1;

    if (tid == 0){ s_cur = (int)atomicAdd(ctr, 1u); s_next = (int)atomicAdd(ctr, 1u); }
    __syncthreads();
    int cur = s_cur, nxt = s_next;
    if (cur >= TOTAL) return;

    const bf* Ahp = (MODE == 0) ? g_xh : g_ah;
    const bf* Alp = (MODE == 0) ? g_xl : g_al;

    auto decode = [&](int id, int& rowA, int& rowB, const bf*& Bh2, const bf*& Bl2, int& z){
        if (MODE == 0){
            z = id >> 10; int r = id & 1023;
            rowB = (r >> 7) * 128; rowA = (r & 127) * 128;
            Bh2 = z == 0 ? g_Wqh : z == 1 ? g_Wkh : g_Wvh;
            Bl2 = z == 0 ? g_Wql : z == 1 ? g_Wkl : g_Wvl;
        } else {
            z = 0;
            rowB = (id >> 7) * 128; rowA = (id & 127) * 128;
            Bh2 = g_Woh; Bl2 = g_Wol;
        }
    };
    auto commitStage = [&](int slot, int rA, int rB, const bf* bh, const bf* bl, int k0){
        uint32_t st_ = sb + (uint32_t)slot * STAGE_BYTES;
        load_tileN<128>(st_,         Ahp, rA, KA, k0, tid);
        load_tileN<128>(st_ + 16384, Alp, rA, KA, k0, tid);
        load_tileN<128>(st_ + 32768, bh,  rB, KA, k0, tid);
        load_tileN<128>(st_ + 49152, bl,  rB, KA, k0, tid);
        cpa_commit();
    };

    int rowA, rowB, zc; const bf *Bh2, *Bl2;
    decode(cur, rowA, rowB, Bh2, Bl2, zc);
    commitStage(0, rowA, rowB, Bh2, Bl2, 0);
    commitStage(1, rowA, rowB, Bh2, Bl2, 64);
    int committed = 2, s = 0;

    int rr = lane & 7, sub = lane >> 3;
    int wm = (w & 1) * 64, wn = (w >> 1) * 32;
    int arow = wm + rr + (sub & 1) * 8;
    int acb0 = (sub >> 1) * 16;
    int brow = wn + rr + (sub >> 1) * 8;
    int bcb0 = (sub & 1) * 16;
    int r0row = lane >> 2, c0 = (lane & 3) * 2;

    while (true){
        float acc[4][4][4];
#pragma unroll
        for (int i = 0; i < 4; i++)
#pragma unroll
            for (int j = 0; j < 4; j++)
#pragma unroll
                for (int c = 0; c < 4; c++) acc[i][j][c] = 0.f;

        for (int kt = 0; kt < NKT; kt++){
            // wait for stage s data, then ONE barrier: it both releases stage s
            // for reading and proves every warp finished reading stage s-1 ≡ s+2,
            // so the commit below (targeting s+2) is safe.
            int allowed = committed - s - 1;
            if (allowed >= 2) cpa_wait2(); else if (allowed == 1) cpa_wait1(); else cpa_wait0();
            __syncthreads();

            int kt2 = kt + 2;
            if (kt2 < NKT){
                commitStage((s + 2) % 3, rowA, rowB, Bh2, Bl2, kt2*64); committed++;
            } else if (nxt < TOTAL){
                int rA2, rB2, z2; const bf *bh2, *bl2;
                decode(nxt, rA2, rB2, bh2, bl2, z2);
                commitStage((s + 2) % 3, rA2, rB2, bh2, bl2, (kt2 - NKT)*64); committed++;
            }

            uint32_t st = sb + (uint32_t)(s % 3) * STAGE_BYTES;
#pragma unroll
            for (int ks = 0; ks < 4; ks++){
                uint32_t ahf[4][4], alf[4][4], bhf[4][2], blf[4][2];
#pragma unroll
                for (int i = 0; i < 4; i++){
                    uint32_t sa = swz((uint32_t)((arow + i*16)*128 + acb0 + ks*32));
                    ldsm4(ahf[i][0], ahf[i][1], ahf[i][2], ahf[i][3], st + sa);
                    ldsm4(alf[i][0], alf[i][1], alf[i][2], alf[i][3], st + 16384 + sa);
                }
#pragma unroll
                for (int j2 = 0; j2 < 2; j2++){
                    uint32_t sa = swz((uint32_t)((brow + j2*16)*128 + bcb0 + ks*32));
                    uint32_t r0, r1, r2, r3;
                    ldsm4(r0, r1, r2, r3, st + 32768 + sa);
                    bhf[j2*2][0] = r0; bhf[j2*2][1] = r1; bhf[j2*2+1][0] = r2; bhf[j2*2+1][1] = r3;
                    ldsm4(r0, r1, r2, r3, st + 49152 + sa);
                    blf[j2*2][0] = r0; blf[j2*2][1] = r1; blf[j2*2+1][0] = r2; blf[j2*2+1][1] = r3;
                }
#pragma unroll
                for (int i = 0; i < 4; i++)
#pragma unroll
                    for (int j = 0; j < 4; j++){
                        mma_bf16(acc[i][j], ahf[i], bhf[j]);
                        mma_bf16(acc[i][j], ahf[i], blf[j]);
                        mma_bf16(acc[i][j], alf[i], bhf[j]);
                    }
            }
            s++;
        }

        int m0 = rowA, n0 = rowB;
        if (MODE == 0 && zc < 2){
            bf* Dh = zc ? g_Kh : g_Qh;
            bf* Dl = zc ? g_Kl : g_Ql;
#pragma unroll
            for (int i = 0; i < 4; i++)
#pragma unroll
                for (int j = 0; j < 4; j++)
#pragma unroll
                    for (int half = 0; half < 2; half++){
                        int row = m0 + wm + i*16 + r0row + half*8;
                        int col = n0 + wn + j*8 + c0;
                        bf h0, l0, h1, l1;
                        split2(acc[i][j][half*2], h0, l0);
                        split2(acc[i][j][half*2 + 1], h1, l1);
                        *(__nv_bfloat162*)&Dh[(size_t)row*Ee + col] = __nv_bfloat162{h0, h1};
                        *(__nv_bfloat162*)&Dl[(size_t)row*Ee + col] = __nv_bfloat162{l0, l1};
                    }
        } else {
            // transpose via 4 passes of 32 rows through the dedicated fb buffer
            int b = m0 / Tt, t0 = m0 % Tt;
            __syncthreads();   // all warps done with k-loop before fb reuse
#pragma unroll
            for (int p = 0; p < 4; p++){
                if ((w & 1) == (p >> 1)){
                    int ibase = (p & 1) * 2;
#pragma unroll
                    for (int ii = 0; ii < 2; ii++)
#pragma unroll
                        for (int j = 0; j < 4; j++)
#pragma unroll
                            for (int half = 0; half < 2; half++){
                                int row = (ibase + ii)*16 + r0row + half*8 - (p & 1)*32;
                                int col = wn + j*8 + c0;
                                fb[row*129 + col]     = acc[ibase + ii][j][half*2];
                                fb[row*129 + col + 1] = acc[ibase + ii][j][half*2 + 1];
                            }
                }
                __syncthreads();
                if (MODE == 0){
                    for (int idx = tid; idx < 4096; idx += 256){
                        int n = idx >> 5, t = idx & 31;
                        bf h, l; split2(fb[t*129 + n], h, l);
                        size_t o = (size_t)(b*Ee + n0 + n)*Tt + t0 + p*32 + t;
                        g_Vth[o] = h; g_Vtl[o] = l;
                    }
                } else {
                    for (int idx = tid; idx < 4096; idx += 256){
                        int n = idx >> 5, t = idx & 31;
                        outp[(size_t)b*CO*Tt + (size_t)(Cc + n0 + n)*Tt + t0 + p*32 + t] = fb[t*129 + n];
                    }
                }
                __syncthreads();
            }
        }

        if (nxt >= TOTAL) break;
        cur = nxt;
        decode(cur, rowA, rowB, Bh2, Bl2, zc);
        if (tid == 0) s_next = (int)atomicAdd(ctr, 1u);
        __syncthreads();
        nxt = s_next;
    }
}

// ================= 128-tile mma kernel for kv (MODE 3) / attn (MODE 4), 1 barrier/k-tile =================
#define MMA_DSM 196608

template<int MODE>
__global__ __launch_bounds__(256, 1) void k_mma(float* __restrict__ outp){
    constexpr int JMAX   = 2;
    constexpr int NBROWS = 64;
    constexpr int NKT    = (MODE == 3) ? 8 : 4;

    extern __shared__ __align__(1024) char dsm[];
    __shared__ float sden[128];
    __shared__ float sKs[256];
    uint32_t sb = s2u(dsm);
    int tid = threadIdx.x, lane = tid & 31, w = tid >> 5;
    int bz = blockIdx.z;
    int m0 = blockIdx.x * 128;

    const bf *Ahp, *Alp, *Bhp, *Blp;
    int rowA0, rowB0, strideA, strideB, k0base = 0;

    if (MODE == 3){
        Ahp = g_Kpth; Alp = g_Kptl;
        rowA0 = bz*Ff + m0; strideA = Tt;
        Bhp = g_Vth; Blp = g_Vtl;
        rowB0 = (bz >> 4)*Ee + (bz & 15)*Dd; strideB = Tt;
        k0base = blockIdx.y * 512;
    } else {
        Ahp = g_Qph; Alp = g_Qpl;
        rowA0 = bz*Tt + m0; strideA = Ff;
        Bhp = g_KVth; Blp = g_KVtl;
        rowB0 = bz*64; strideB = Ff;
    }

    if (MODE == 4){
        if (tid < 128) sden[tid] = 0.f;
        sKs[tid] = g_Ksum[bz*Ff + tid];
    }

    float acc[4][JMAX][4];
#pragma unroll
    for (int i = 0; i < 4; i++)
#pragma unroll
        for (int j = 0; j < JMAX; j++)
#pragma unroll
            for (int c = 0; c < 4; c++) acc[i][j][c] = 0.f;

#define LOADSTG(s, k0) do { \
        uint32_t st_ = sb + (uint32_t)(s)*STAGE_BYTES; \
        load_tileN<128>(st_,         Ahp, rowA0, strideA, (k0), tid); \
        load_tileN<128>(st_ + 16384, Alp, rowA0, strideA, (k0), tid); \
        load_tileN<NBROWS>(st_ + 32768,                Bhp, rowB0, strideB, (k0), tid); \
        load_tileN<NBROWS>(st_ + 32768 + NBROWS*128,   Blp, rowB0, strideB, (k0), tid); \
        cpa_commit(); \
    } while(0)

    LOADSTG(0, k0base);
    if (NKT > 1) LOADSTG(1, k0base + 64);
    int committed = (NKT > 1) ? 2 : 1;

    int rr = lane & 7, sub = lane >> 3;
    int wm = (w & 1) * 64, wn = (w >> 1) * (JMAX * 8);
    int arow = wm + rr + (sub & 1) * 8;
    int acb0 = (sub >> 1) * 16;
    int brow = wn + rr + (sub >> 1) * 8;
    int bcb0 = (sub & 1) * 16;
    const uint32_t blo = 32768u + NBROWS*128u;

    for (int kt = 0; kt < NKT; kt++){
        int allowed = committed - kt - 1;
        if (allowed >= 2) cpa_wait2(); else if (allowed == 1) cpa_wait1(); else cpa_wait0();
        __syncthreads();
        if (kt + 2 < NKT){ LOADSTG((kt + 2) % 3, k0base + (kt + 2)*64); committed++; }

        uint32_t st = sb + (uint32_t)(kt % 3) * STAGE_BYTES;
#pragma unroll
        for (int ks = 0; ks < 4; ks++){
            uint32_t ahf[4][4], alf[4][4], bhf[JMAX][2], blf[JMAX][2];
#pragma unroll
            for (int i = 0; i < 4; i++){
                uint32_t sa = swz((uint32_t)((arow + i*16)*128 + acb0 + ks*32));
                ldsm4(ahf[i][0], ahf[i][1], ahf[i][2], ahf[i][3], st + sa);
                ldsm4(alf[i][0], alf[i][1], alf[i][2], alf[i][3], st + 16384 + sa);
            }
            {
                uint32_t sa = swz((uint32_t)(brow*128 + bcb0 + ks*32));
                uint32_t r0, r1, r2, r3;
                ldsm4(r0, r1, r2, r3, st + 32768 + sa);
                bhf[0][0] = r0; bhf[0][1] = r1; bhf[1][0] = r2; bhf[1][1] = r3;
                ldsm4(r0, r1, r2, r3, st + blo + sa);
                blf[0][0] = r0; blf[0][1] = r1; blf[1][0] = r2; blf[1][1] = r3;
            }
#pragma unroll
            for (int i = 0; i < 4; i++)
#pragma unroll
                for (int j = 0; j < JMAX; j++){
                    mma_bf16(acc[i][j], ahf[i], bhf[j]);
                    mma_bf16(acc[i][j], ahf[i], blf[j]);
                    mma_bf16(acc[i][j], alf[i], bhf[j]);
                }
        }
        if (MODE == 4){
            int row = tid & 127, fh = (tid >> 7) * 32;
            const char* sp = dsm + (size_t)(kt % 3) * STAGE_BYTES;
            float part = 0.f;
#pragma unroll
            for (int jj = 0; jj < 32; jj++){
                int fl = fh + ((jj + lane) & 31);
                uint32_t off = swz((uint32_t)(row*128 + fl*2));
                float hi = __bfloat162float(*(const bf*)(sp + off));
                float lo = __bfloat162float(*(const bf*)(sp + 16384 + off));
                part += (hi + lo) * sKs[kt*64 + fl];
            }
            atomicAdd(&sden[row], part);
        }
    }
#undef LOADSTG

    int r0row = lane >> 2, c0 = (lane & 3) * 2;
    float* fb = (float*)dsm;
    __syncthreads();   // k-loop fully done before fb reuse / sden reads

    if (MODE == 3){
#pragma unroll
        for (int i = 0; i < 4; i++)
#pragma unroll
            for (int j = 0; j < JMAX; j++)
#pragma unroll
                for (int half = 0; half < 2; half++){
                    int row = wm + i*16 + r0row + half*8;
                    int col = wn + j*8 + c0;
                    fb[row*129 + col]     = acc[i][j][half*2];
                    fb[row*129 + col + 1] = acc[i][j][half*2 + 1];
                }
        __syncthreads();
        for (int idx = tid; idx < 8192; idx += 256){
            int n = idx >> 7, f = idx & 127;
            atomicAdd(&g_KVt[((size_t)bz*64 + n)*Ff + m0 + f], fb[f*129 + n]);
        }
    } else {
        int b = bz >> 4, h = bz & 15;
#pragma unroll
        for (int i = 0; i < 4; i++)
#pragma unroll
            for (int half = 0; half < 2; half++){
                int row = wm + i*16 + r0row + half*8;
                float inv = 1.0f / fmaxf(sden[row], 1e-6f);
#pragma unroll
                for (int j = 0; j < JMAX; j++){
                    int col = wn + j*8 + c0;
                    bf h0, l0, h1, l1;
                    split2(acc[i][j][half*2] * inv, h0, l0);
                    split2(acc[i][j][half*2 + 1] * inv, h1, l1);
                    size_t o = (size_t)(b*Tt + m0 + row)*Ee + h*Dd + col;
                    *(__nv_bfloat162*)&g_ah[o] = __nv_bfloat162{h0, h1};
                    *(__nv_bfloat162*)&g_al[o] = __nv_bfloat162{l0, l1};
                }
            }
    }
}

// ================= feature-map kernel: proj resident, Q AND K in one block (8 m-iters) =================
#define FEAT_DSM (32768 + 65536 + 66048)

__global__ __launch_bounds__(256, 1) void k_featm(){
    extern __shared__ __align__(1024) char dsm[];
    uint32_t sb = s2u(dsm);
    int tid = threadIdx.x, lane = tid & 31, w = tid >> 5;
    int bh = blockIdx.z;
    int m0 = blockIdx.x * 512, n0 = blockIdx.y * 128;
    int hoff = (bh & 15)*Dd;
    int rowBase = (bh >> 4)*Tt + m0;

    auto srcH = [&](int it){ return (it < 4 ? g_Qh : g_Kh) + hoff; };
    auto srcL = [&](int it){ return (it < 4 ? g_Ql : g_Kl) + hoff; };

    load_tileN<128>(sb,         g_ph, n0, Dd, 0, tid);
    load_tileN<128>(sb + 16384, g_pl, n0, Dd, 0, tid);
    load_tileN<128>(sb + 32768,         srcH(0), rowBase, Ee, 0, tid);
    load_tileN<128>(sb + 32768 + 16384, srcL(0), rowBase, Ee, 0, tid);
    cpa_commit();
    load_tileN<128>(sb + 65536,         srcH(1), rowBase + 128, Ee, 0, tid);
    load_tileN<128>(sb + 65536 + 16384, srcL(1), rowBase + 128, Ee, 0, tid);
    cpa_commit();

    int rr = lane & 7, sub = lane >> 3;
    int wm = (w & 1) * 64, wn = (w >> 1) * 32;
    int arow = wm + rr + (sub & 1) * 8;
    int acb0 = (sub >> 1) * 16;
    int brow = wn + rr + (sub >> 1) * 8;
    int bcb0 = (sub & 1) * 16;
    float* fb = (float*)(dsm + 32768 + 65536);

    for (int it = 0; it < 8; it++){
        uint32_t stA = sb + 32768 + (uint32_t)(it & 1) * 32768;
        if (it < 7) cpa_wait1(); else cpa_wait0();
        __syncthreads();

        float acc[4][4][4];
#pragma unroll
        for (int i = 0; i < 4; i++)
#pragma unroll
            for (int j = 0; j < 4; j++)
#pragma unroll
                for (int c = 0; c < 4; c++) acc[i][j][c] = 0.f;

#pragma unroll
        for (int ks = 0; ks < 4; ks++){
            uint32_t ahf[4][4], alf[4][4], bhf[4][2], blf[4][2];
#pragma unroll
            for (int i = 0; i < 4; i++){
                uint32_t sa = swz((uint32_t)((arow + i*16)*128 + acb0 + ks*32));
                ldsm4(ahf[i][0], ahf[i][1], ahf[i][2], ahf[i][3], stA + sa);
                ldsm4(alf[i][0], alf[i][1], alf[i][2], alf[i][3], stA + 16384 + sa);
            }
#pragma unroll
            for (int j2 = 0; j2 < 2; j2++){
                uint32_t sa = swz((uint32_t)((brow + j2*16)*128 + bcb0 + ks*32));
                uint32_t r0, r1, r2, r3;
                ldsm4(r0, r1, r2, r3, sb + sa);
                bhf[j2*2][0] = r0; bhf[j2*2][1] = r1; bhf[j2*2+1][0] = r2; bhf[j2*2+1][1] = r3;
                ldsm4(r0, r1, r2, r3, sb + 16384 + sa);
                blf[j2*2][0] = r0; blf[j2*2][1] = r1; blf[j2*2+1][0] = r2; blf[j2*2+1][1] = r3;
            }
#pragma unroll
            for (int i = 0; i < 4; i++)
#pragma unroll
                for (int j = 0; j < 4; j++){
                    mma_bf16(acc[i][j], ahf[i], bhf[j]);
                    mma_bf16(acc[i][j], ahf[i], blf[j]);
                    mma_bf16(acc[i][j], alf[i], bhf[j]);
                }
        }
        __syncthreads();
        if (it + 2 < 8){
            load_tileN<128>(stA,         srcH(it + 2), rowBase + ((it + 2) & 3)*128, Ee, 0, tid);
            load_tileN<128>(stA + 16384, srcL(it + 2), rowBase + ((it + 2) & 3)*128, Ee, 0, tid);
            cpa_commit();
        }

        int r0row = lane >> 2, c0 = (lane & 3) * 2;
        int mt = (it & 3) * 128;
        if (it < 4){
#pragma unroll
            for (int i = 0; i < 4; i++)
#pragma unroll
                for (int j = 0; j < 4; j++)
#pragma unroll
                    for (int half = 0; half < 2; half++){
                        int row = wm + i*16 + r0row + half*8;
                        int col = wn + j*8 + c0;
                        bf h0, l0, h1, l1;
                        split2(expf(acc[i][j][half*2]) + EPS, h0, l0);
                        split2(expf(acc[i][j][half*2 + 1]) + EPS, h1, l1);
                        size_t o = (size_t)(bh*Tt + m0 + mt + row)*Ff + n0 + col;
                        *(__nv_bfloat162*)&g_Qph[o] = __nv_bfloat162{h0, h1};
                        *(__nv_bfloat162*)&g_Qpl[o] = __nv_bfloat162{l0, l1};
                    }
        } else {
#pragma unroll
            for (int i = 0; i < 4; i++)
#pragma unroll
                for (int j = 0; j < 4; j++)
#pragma unroll
                    for (int half = 0; half < 2; half++){
                        int row = wm + i*16 + r0row + half*8;
                        int col = wn + j*8 + c0;
                        fb[row*129 + col]     = expf(acc[i][j][half*2]) + EPS;
                        fb[row*129 + col + 1] = expf(acc[i][j][half*2 + 1]) + EPS;
                    }
            __syncthreads();
            for (int idx = tid; idx < 16384; idx += 256){
                int f = idx >> 7, t = idx & 127;
                bf h, l; split2(fb[t*129 + f], h, l);
                size_t o = (size_t)(bh*Ff + n0 + f)*Tt + m0 + mt + t;
                g_Kpth[o] = h; g_Kptl[o] = l;
            }
            {
                int f = tid >> 1, th = tid & 1;
                float s = 0.f;
#pragma unroll 8
                for (int t = th*64; t < th*64 + 64; t++) s += fb[t*129 + f];
                atomicAdd(&g_Ksum[bh*Ff + n0 + f], s);
            }
            __syncthreads();
        }
    }
}

// ================= launch =================
extern "C" void kernel_launch(void* const* d_in, const int* in_sizes, int n_in,
                              void* d_out, int out_size) {
    const float* x    = (const float*)d_in[0];
    const float* Wq   = (const float*)d_in[1];
    const float* Wk   = (const float*)d_in[2];
    const float* Wv   = (const float*)d_in[3];
    const float* Wo   = (const float*)d_in[4];
    const float* proj = (const float*)d_in[5];
    float* out = (float*)d_out;

    cudaFuncSetAttribute(k_mmaP<0>, cudaFuncAttributeMaxDynamicSharedMemorySize, PERS_DSM);
    cudaFuncSetAttribute(k_mmaP<1>, cudaFuncAttributeMaxDynamicSharedMemorySize, PERS_DSM);
    cudaFuncSetAttribute(k_mma<3>,  cudaFuncAttributeMaxDynamicSharedMemorySize, MMA_DSM);
    cudaFuncSetAttribute(k_mma<4>,  cudaFuncAttributeMaxDynamicSharedMemorySize, MMA_DSM);
    cudaFuncSetAttribute(k_featm,   cudaFuncAttributeMaxDynamicSharedMemorySize, FEAT_DSM);

    k_prep_proj<<<(Bb*Hh*64*Ff + 255)/256, 256>>>(proj);
    k_prep_x<<<dim3(Tt/32, Cc/32, Bb), dim3(32, 8)>>>(x, out);
    k_prep_w<<<dim3(Ee/32, Ee/32, 4), dim3(32, 8)>>>(Wq, Wk, Wv, Wo);

    k_mmaP<0><<<148, 256, PERS_DSM>>>(nullptr);                            // QKV (persistent)
    k_featm<<<dim3(Tt/512, Ff/128, Bb*Hh), 256, FEAT_DSM>>>();             // Qp + Kp + Ksum
    k_mma<3><<<dim3(Ff/128, 8, Bb*Hh), 256, MMA_DSM>>>(nullptr);           // KV
    k_cvt_kv<<<(Bb*Hh*64*Ff + 255)/256, 256>>>();
    k_mma<4><<<dim3(Tt/128, 1, Bb*Hh), 256, MMA_DSM>>>(nullptr);           // attn
    k_mmaP<1><<<148, 256, PERS_DSM>>>(out);                                // Wo + concat (persistent)
}